// round 8
// baseline (speedup 1.0000x reference)
#include <cuda_runtime.h>
#include <math.h>

// BATCH=128, SEQ_LEN=4096, HIDDEN=512, WINDOW=7 (W2=49), GRID=256
#define HIDDEN   512
#define WINDOW   7
#define W2       (WINDOW * WINDOW)
#define NTHREADS 512
#define NWARPS   (NTHREADS / 32)    // 16
#define MAXW     4                  // windows per warp: w = wid + 16*j

__global__ __launch_bounds__(NTHREADS, 1)
void hilbert_attn_kernel(const float* __restrict__ q,      // (B,1,H)
                         const float* __restrict__ k,      // (B,S,H)
                         const float* __restrict__ v,      // (B,S,H)
                         const int*   __restrict__ qpos,   // (B,)
                         const float* __restrict__ dscale, // ()
                         const float* __restrict__ lbias,  // (W2,)
                         const int*   __restrict__ hcoords,// (MAX_SEQ,2)
                         const int*   __restrict__ hinv,   // (GRID,GRID)
                         float*       __restrict__ out,    // (B,H)
                         int S, int grid_n)
{
    const int b    = blockIdx.x;
    const int tid  = threadIdx.x;
    const int wid  = tid >> 5;
    const int lane = tid & 31;
    const unsigned FULL = 0xffffffffu;

    __shared__ float s_e[W2];     // unnormalized exp weight per window (0 if invalid)
    __shared__ int   s_pos[W2];   // safe position per window (0 if invalid)

    // ---- q slice into registers ----
    float4 qv[4];
    {
        const float4* qg = reinterpret_cast<const float4*>(q + (size_t)b * HIDDEN);
        #pragma unroll
        for (int c = 0; c < 4; ++c) qv[c] = qg[c * 32 + lane];
    }

    // ---- warp-autonomous window resolution (no barriers) ----
    const int p   = qpos[b];
    const int qx  = hcoords[2 * p];
    const int qy  = hcoords[2 * p + 1];
    const float scale = dscale[0];

    // round A: lane l -> window l (0..31)
    int dxA = lane / WINDOW - (WINDOW / 2);
    int dyA = lane % WINDOW - (WINDOW / 2);
    int nxA = qx + dxA, nyA = qy + dyA;
    bool ingA = (nxA >= 0) & (nxA < grid_n) & (nyA >= 0) & (nyA < grid_n);
    int posA = ingA ? hinv[nxA * grid_n + nyA] : -1;
    bool vA = ingA && (posA >= 0) && (posA < S);

    // round B: lane l -> window l+32 (32..48)
    int wB = lane + 32;
    bool inB = (wB < W2);
    int dxB = inB ? (wB / WINDOW - (WINDOW / 2)) : 0;
    int dyB = inB ? (wB % WINDOW - (WINDOW / 2)) : 0;
    int nxB = qx + dxB, nyB = qy + dyB;
    bool ingB = inB & (nxB >= 0) & (nxB < grid_n) & (nyB >= 0) & (nyB < grid_n);
    int posB = ingB ? hinv[nxB * grid_n + nyB] : -1;
    bool vB = ingB && (posB >= 0) && (posB < S);

    const unsigned m0 = __ballot_sync(FULL, vA);
    const unsigned m1 = __ballot_sync(FULL, vB);

    // warp 0 publishes safe positions for the whole window set
    if (wid == 0) {
        s_pos[lane] = vA ? posA : 0;
        if (lane < W2 - 32) s_pos[32 + lane] = vB ? posB : 0;
    }

    // ---- this warp's 4 windows: w = wid + 16*j ----
    int   mypos[MAXW];
    bool  myok[MAXW];
    float mylw[MAXW];
    #pragma unroll
    for (int j = 0; j < MAXW; ++j) {
        int w = wid + 16 * j;
        bool exists = (w < W2);
        int pj = (j < 2) ? __shfl_sync(FULL, posA, w & 31)
                         : __shfl_sync(FULL, posB, (w - 32) & 31);
        bool ok = exists && (w < 32 ? ((m0 >> w) & 1u) : ((m1 >> (w - 32)) & 1u));
        mypos[j] = ok ? pj : 0;
        myok[j]  = ok;
        float lw = 0.0f;
        if (ok) {
            int c;
            if (w < 32) {
                unsigned mm = (w == 31) ? 0xffffffffu : ((2u << w) - 1u);
                c = __popc(m0 & mm) - 1;
            } else {
                c = __popc(m0) + __popc(m1 & ((2u << (w - 32)) - 1u)) - 1;
            }
            int dist = abs(w / WINDOW - 3) + abs(w % WINDOW - 3);
            lw = __logf(__expf(-(float)dist * scale) + __ldg(lbias + c) + 1e-8f);
        }
        mylw[j] = lw;
    }

    const float* kb = k + (size_t)b * S * HIDDEN;
    const float4* kr[MAXW];
    #pragma unroll
    for (int j = 0; j < MAXW; ++j)
        kr[j] = reinterpret_cast<const float4*>(kb + (size_t)mypos[j] * HIDDEN);

    // ---- dots: chunk-major, unconditional loads, high MLP ----
    float d[MAXW] = {0.f, 0.f, 0.f, 0.f};
    #pragma unroll
    for (int c = 0; c < 4; ++c) {
        float4 kk[MAXW];
        #pragma unroll
        for (int j = 0; j < MAXW; ++j) kk[j] = kr[j][c * 32 + lane];
        #pragma unroll
        for (int j = 0; j < MAXW; ++j)
            d[j] += kk[j].x * qv[c].x + kk[j].y * qv[c].y
                  + kk[j].z * qv[c].z + kk[j].w * qv[c].w;
    }
    #pragma unroll
    for (int off = 16; off > 0; off >>= 1) {
        #pragma unroll
        for (int j = 0; j < MAXW; ++j)
            d[j] += __shfl_xor_sync(FULL, d[j], off);
    }

    // ---- publish unnormalized exp weights (lane 0) ----
    const float inv_sqrt_h = 0.04419417382415922f; // 1/sqrt(512)
    if (lane == 0) {
        #pragma unroll
        for (int j = 0; j < MAXW; ++j) {
            int w = wid + 16 * j;
            if (w < W2)
                s_e[w] = myok[j] ? __expf(d[j] * inv_sqrt_h + mylw[j]) : 0.0f;
        }
    }
    __syncthreads();   // the ONLY block barrier

    // ---- transposed V phase: thread owns one hidden dim, all 49 windows ----
    const float* vb = v + (size_t)b * S * HIDDEN + tid;
    float acc  = 0.0f;
    float esum = 0.0f;
    #pragma unroll
    for (int w = 0; w < W2; ++w) {
        float e  = s_e[w];            // broadcast LDS
        int pos  = s_pos[w];          // broadcast LDS
        acc  += e * __ldg(vb + (size_t)pos * HIDDEN);
        esum += e;
    }
    out[(size_t)b * HIDDEN + tid] = acc / esum;
}

extern "C" void kernel_launch(void* const* d_in, const int* in_sizes, int n_in,
                              void* d_out, int out_size)
{
    const float* q       = (const float*)d_in[0];
    const float* k       = (const float*)d_in[1];
    const float* v       = (const float*)d_in[2];
    const int*   qpos    = (const int*)d_in[3];
    const float* dscale  = (const float*)d_in[4];
    const float* lbias   = (const float*)d_in[5];
    const int*   hcoords = (const int*)d_in[6];
    const int*   hinv    = (const int*)d_in[7];
    float*       out     = (float*)d_out;

    int B = in_sizes[3];                      // 128
    int H = in_sizes[0] / B;                  // 512
    int S = in_sizes[1] / (B * H);            // 4096
    int inv_elems = in_sizes[7];              // grid*grid
    int grid_n = 1;
    while (grid_n * grid_n < inv_elems) grid_n <<= 1;  // 256

    hilbert_attn_kernel<<<B, NTHREADS>>>(q, k, v, qpos, dscale, lbias,
                                         hcoords, hinv, out, S, grid_n);
}